// round 4
// baseline (speedup 1.0000x reference)
#include <cuda_runtime.h>

// Problem constants: B=32, S1=14, S2=14, NC=2, DC=16, F=32, I=8
#define NROWS   200704      // B*S1*S2*NC*DC
#define DE      32          // NC*DC (rows repeat weights with period 32)
#define HALF    51380224    // NROWS * F * I  (elements per output tensor)

__device__ __forceinline__ float ex2a(float x) {
    float y; asm("ex2.approx.ftz.f32 %0, %1;" : "=f"(y) : "f"(x)); return y;
}
__device__ __forceinline__ float rcpa(float x) {
    float y; asm("rcp.approx.ftz.f32 %0, %1;" : "=f"(y) : "f"(x)); return y;
}

// Lane layout: lane = g*8 + i  (g = f-group 0..3, i = capsule-index 0..7).
// Lane owns output elements f*8+i for f = g*8 .. g*8+7  (8 elems per tensor).
// All f-reductions = 7 in-register ops + butterfly over {xor 8, xor 16}.
__global__ void __launch_bounds__(256)
mhsa_main(const float* __restrict__ U,
          const float* __restrict__ Wt,
          const float* __restrict__ Wa,
          float* __restrict__ outC,
          float* __restrict__ outUI)
{
    const int warp = (blockIdx.x * blockDim.x + threadIdx.x) >> 5;
    const int lane = threadIdx.x & 31;
    if (warp >= NROWS) return;

    const int row = warp;
    const int de  = row & (DE - 1);
    const int g   = lane >> 3;      // f-group: f = g*8 + k
    const int i   = lane & 7;       // capsule index

    // ---- U values for this lane's 8 f's (two float4, broadcast across 8 lanes)
    const float4* u4 = (const float4*)(U + row * 32 + g * 8);
    const float4 uA = u4[0];
    const float4 uB = u4[1];
    float u[8] = {uA.x, uA.y, uA.z, uA.w, uB.x, uB.y, uB.z, uB.w};

    // ---- weights: Wa/Wt[de*256 + (g*8+k)*8 + i]  (L1-resident, coalesced 32B sectors)
    const float* wa_p = Wa + de * 256 + g * 64 + i;
    const float* wt_p = Wt + de * 256 + g * 64 + i;
    float wa[8], wt[8];
    #pragma unroll
    for (int k = 0; k < 8; ++k) { wa[k] = wa_p[k * 8]; wt[k] = wt_p[k * 8]; }

    // ---- U_hat_I = u * W_affine ; store immediately; accumulate sum of squares
    float* oUI = outUI + (size_t)row * 256 + g * 64 + i;
    float ui[8];
    float sq = 0.0f;
    #pragma unroll
    for (int k = 0; k < 8; ++k) {
        ui[k] = u[k] * wa[k];
        oUI[k * 8] = ui[k];
        sq = fmaf(ui[k], ui[k], sq);
    }

    // ---- per-thread max over this lane's 8 Wt values (for softmax stability)
    float wm = wt[0];
    #pragma unroll
    for (int k = 1; k < 8; ++k) wm = fmaxf(wm, wt[k]);

    // ---- complete both f-reductions across the 4 g-groups (scalar, 2 steps)
    #pragma unroll
    for (int m = 8; m <= 16; m <<= 1) {
        sq += __shfl_xor_sync(0xffffffffu, sq, m);
        wm  = fmaxf(wm, __shfl_xor_sync(0xffffffffu, wm, m));
    }

    // ds = diag * log2e (fold /sqrt(16) and log2e); diag >= 0 so row-max = ds*wm
    const float SC = 0.25f * 1.4426950408889634f;
    const float ds = sq * SC;
    const float mx = ds * wm;

    // ---- exponentials + f-sum
    float e[8];
    float s = 0.0f;
    #pragma unroll
    for (int k = 0; k < 8; ++k) {
        e[k] = ex2a(fmaf(ds, wt[k], -mx));
        s += e[k];
    }
    #pragma unroll
    for (int m = 8; m <= 16; m <<= 1)
        s += __shfl_xor_sync(0xffffffffu, s, m);

    const float inv = rcpa(s);

    // ---- softmax outputs
    float* oC = outC + (size_t)row * 256 + g * 64 + i;
    #pragma unroll
    for (int k = 0; k < 8; ++k)
        oC[k * 8] = e[k] * inv;
}

extern "C" void kernel_launch(void* const* d_in, const int* in_sizes, int n_in,
                              void* d_out, int out_size)
{
    const float* U  = (const float*)d_in[0];   // U_hat    (6,422,528)
    const float* Wt = (const float*)d_in[1];   // W_t      (8,192)
    const float* Wa = (const float*)d_in[2];   // W_affine (8,192)
    float* outC  = (float*)d_out;              // C first (return order)
    float* outUI = (float*)d_out + HALF;       // then U_hat_I

    const int warps_per_block = 8;              // 256 threads
    const int blocks = NROWS / warps_per_block; // 25088
    mhsa_main<<<blocks, 256>>>(U, Wt, Wa, outC, outUI);
}

// round 7
// speedup vs baseline: 1.4326x; 1.4326x over previous
#include <cuda_runtime.h>

// Problem constants: B=32, S1=14, S2=14, NC=2, DC=16, F=32, I=8
#define NROWS   200704      // B*S1*S2*NC*DC
#define DE      32          // NC*DC (rows repeat weights with period 32)
#define HALF    51380224    // NROWS * F * I  (elements per output tensor)
#define RPW     8           // rows per warp (all share one de)
#define NWARPS  (NROWS / RPW)   // 25088

__device__ __forceinline__ float ex2a(float x) {
    float y; asm("ex2.approx.ftz.f32 %0, %1;" : "=f"(y) : "f"(x)); return y;
}
__device__ __forceinline__ float rcpa(float x) {
    float y; asm("rcp.approx.ftz.f32 %0, %1;" : "=f"(y) : "f"(x)); return y;
}

// Lane layout (R2): lane owns f_lo = lane>>1 and f_hi = f_lo+16, with the 4
// consecutive i's (lane&1)*4.. +3 as a float4. All global accesses are fully
// coalesced 512B STG.128/LDG.128. Each warp handles RPW rows sharing one de,
// so weights + the exact max_f(Wt) butterfly are paid once per warp.
__global__ void __launch_bounds__(256)
mhsa_main(const float* __restrict__ U,
          const float* __restrict__ Wt,
          const float* __restrict__ Wa,
          float* __restrict__ outC,
          float* __restrict__ outUI)
{
    const int w    = (blockIdx.x * blockDim.x + threadIdx.x) >> 5;
    const int lane = threadIdx.x & 31;
    if (w >= NWARPS) return;

    const int de = w & (DE - 1);
    const int j0 = (w >> 5) * RPW;      // row = de + 32*j, j = j0..j0+RPW-1

    // ---- weights, once per warp (L1-resident)
    const float4* wa4 = (const float4*)(Wa + de * 256);
    const float4* wt4 = (const float4*)(Wt + de * 256);
    const float4 waL = wa4[lane];
    const float4 waH = wa4[lane + 32];
    const float4 wtL = wt4[lane];
    const float4 wtH = wt4[lane + 32];

    // ---- exact mw[i] = max_f Wt[de,f,i], once per warp (parity butterfly)
    float4 wm;
    wm.x = fmaxf(wtL.x, wtH.x);
    wm.y = fmaxf(wtL.y, wtH.y);
    wm.z = fmaxf(wtL.z, wtH.z);
    wm.w = fmaxf(wtL.w, wtH.w);
    #pragma unroll
    for (int m = 2; m <= 16; m <<= 1) {
        wm.x = fmaxf(wm.x, __shfl_xor_sync(0xffffffffu, wm.x, m));
        wm.y = fmaxf(wm.y, __shfl_xor_sync(0xffffffffu, wm.y, m));
        wm.z = fmaxf(wm.z, __shfl_xor_sync(0xffffffffu, wm.z, m));
        wm.w = fmaxf(wm.w, __shfl_xor_sync(0xffffffffu, wm.w, m));
    }

    const int f_lo = lane >> 1;
    const float SC = 0.25f * 1.4426950408889634f;   // fold /sqrt(16) and log2e

    #pragma unroll 2
    for (int t = 0; t < RPW; ++t) {
        const int row = de + ((j0 + t) << 5);

        // ---- U row: lane l holds f=l; grab this lane's two f's
        const float u_mine = U[row * 32 + lane];
        const float u_lo = __shfl_sync(0xffffffffu, u_mine, f_lo);
        const float u_hi = __shfl_sync(0xffffffffu, u_mine, f_lo + 16);

        // ---- U_hat_I = u * W_affine
        float4 uiL, uiH;
        uiL.x = u_lo * waL.x; uiL.y = u_lo * waL.y; uiL.z = u_lo * waL.z; uiL.w = u_lo * waL.w;
        uiH.x = u_hi * waH.x; uiH.y = u_hi * waH.y; uiH.z = u_hi * waH.z; uiH.w = u_hi * waH.w;

        float4* oUI = (float4*)(outUI + (size_t)row * 256);
        oUI[lane]      = uiL;
        oUI[lane + 32] = uiH;

        // ---- diag[i] = sum_f ui^2 / 4  (parity butterfly)
        float4 sq;
        sq.x = fmaf(uiL.x, uiL.x, uiH.x * uiH.x);
        sq.y = fmaf(uiL.y, uiL.y, uiH.y * uiH.y);
        sq.z = fmaf(uiL.z, uiL.z, uiH.z * uiH.z);
        sq.w = fmaf(uiL.w, uiL.w, uiH.w * uiH.w);
        #pragma unroll
        for (int m = 2; m <= 16; m <<= 1) {
            sq.x += __shfl_xor_sync(0xffffffffu, sq.x, m);
            sq.y += __shfl_xor_sync(0xffffffffu, sq.y, m);
            sq.z += __shfl_xor_sync(0xffffffffu, sq.z, m);
            sq.w += __shfl_xor_sync(0xffffffffu, sq.w, m);
        }

        // ds = diag*log2e; diag >= 0 so row max of ds*wt = ds*wm (exact)
        float4 ds, mx;
        ds.x = sq.x * SC; ds.y = sq.y * SC; ds.z = sq.z * SC; ds.w = sq.w * SC;
        mx.x = ds.x * wm.x; mx.y = ds.y * wm.y; mx.z = ds.z * wm.z; mx.w = ds.w * wm.w;

        float4 eL, eH;
        eL.x = ex2a(fmaf(ds.x, wtL.x, -mx.x));
        eL.y = ex2a(fmaf(ds.y, wtL.y, -mx.y));
        eL.z = ex2a(fmaf(ds.z, wtL.z, -mx.z));
        eL.w = ex2a(fmaf(ds.w, wtL.w, -mx.w));
        eH.x = ex2a(fmaf(ds.x, wtH.x, -mx.x));
        eH.y = ex2a(fmaf(ds.y, wtH.y, -mx.y));
        eH.z = ex2a(fmaf(ds.z, wtH.z, -mx.z));
        eH.w = ex2a(fmaf(ds.w, wtH.w, -mx.w));

        float4 s;
        s.x = eL.x + eH.x; s.y = eL.y + eH.y; s.z = eL.z + eH.z; s.w = eL.w + eH.w;
        #pragma unroll
        for (int m = 2; m <= 16; m <<= 1) {
            s.x += __shfl_xor_sync(0xffffffffu, s.x, m);
            s.y += __shfl_xor_sync(0xffffffffu, s.y, m);
            s.z += __shfl_xor_sync(0xffffffffu, s.z, m);
            s.w += __shfl_xor_sync(0xffffffffu, s.w, m);
        }

        float4 inv;
        inv.x = rcpa(s.x); inv.y = rcpa(s.y); inv.z = rcpa(s.z); inv.w = rcpa(s.w);

        float4 cL, cH;
        cL.x = eL.x * inv.x; cL.y = eL.y * inv.y; cL.z = eL.z * inv.z; cL.w = eL.w * inv.w;
        cH.x = eH.x * inv.x; cH.y = eH.y * inv.y; cH.z = eH.z * inv.z; cH.w = eH.w * inv.w;

        float4* oC = (float4*)(outC + (size_t)row * 256);
        oC[lane]      = cL;
        oC[lane + 32] = cH;
    }
}

extern "C" void kernel_launch(void* const* d_in, const int* in_sizes, int n_in,
                              void* d_out, int out_size)
{
    const float* U  = (const float*)d_in[0];   // U_hat    (6,422,528)
    const float* Wt = (const float*)d_in[1];   // W_t      (8,192)
    const float* Wa = (const float*)d_in[2];   // W_affine (8,192)
    float* outC  = (float*)d_out;              // C first (return order)
    float* outUI = (float*)d_out + HALF;       // then U_hat_I

    const int threads = 256;                      // 8 warps
    const int blocks  = NWARPS / (threads / 32);  // 3136
    mhsa_main<<<blocks, threads>>>(U, Wt, Wa, outC, outUI);
}